// round 1
// baseline (speedup 1.0000x reference)
#include <cuda_runtime.h>

#define B_   2
#define S_   2048
#define H_   16
#define D_   64
#define E_   1024
#define TE_  3072
#define MTOT (B_ * S_)   // 4096

// Scratch (alloc-free): qkv projection output and attention output
__device__ float g_qkv[(size_t)MTOT * TE_];   // [B,S,3E] == [4096, 3072]
__device__ float g_vals[(size_t)MTOT * E_];   // [B,S,E]  == [4096, 1024]

// ---------------------------------------------------------------------------
// SGEMM (NT): C[M,N] = A[M,K] * B[N,K]^T + bias[N]
// 128x128x8 block tile, 256 threads, 8x8 per-thread micro-tile.
// M % 128 == 0, N % 128 == 0, K % 8 == 0 guaranteed by our shapes.
// ---------------------------------------------------------------------------
__global__ __launch_bounds__(256)
void sgemm_nt_bias(const float* __restrict__ A, const float* __restrict__ Bw,
                   const float* __restrict__ bias, float* __restrict__ C,
                   int M, int N, int K)
{
    const int BM = 128, BN = 128, BK = 8;
    __shared__ float As[BK][BM];
    __shared__ float Bs[BK][BN];

    const int t  = threadIdx.x;
    const int bm = blockIdx.y * BM;
    const int bn = blockIdx.x * BN;

    const int lrow = t >> 1;            // 0..127 (row within tile to load)
    const int lcol = (t & 1) * 4;       // 0 or 4 (k-offset, float4)

    const int ty = t >> 4;              // 0..15
    const int tx = t & 15;              // 0..15

    const float* Ap = A  + (size_t)(bm + lrow) * K + lcol;
    const float* Bp = Bw + (size_t)(bn + lrow) * K + lcol;

    float acc[8][8];
    #pragma unroll
    for (int i = 0; i < 8; i++)
        #pragma unroll
        for (int j = 0; j < 8; j++) acc[i][j] = 0.f;

    for (int k0 = 0; k0 < K; k0 += BK) {
        float4 av = *(const float4*)(Ap + k0);
        float4 bv = *(const float4*)(Bp + k0);
        __syncthreads();   // protect previous iteration's smem reads
        As[lcol + 0][lrow] = av.x;
        As[lcol + 1][lrow] = av.y;
        As[lcol + 2][lrow] = av.z;
        As[lcol + 3][lrow] = av.w;
        Bs[lcol + 0][lrow] = bv.x;
        Bs[lcol + 1][lrow] = bv.y;
        Bs[lcol + 2][lrow] = bv.z;
        Bs[lcol + 3][lrow] = bv.w;
        __syncthreads();

        #pragma unroll
        for (int kk = 0; kk < BK; kk++) {
            float4 a0 = *(const float4*)&As[kk][ty * 8];
            float4 a1 = *(const float4*)&As[kk][ty * 8 + 4];
            float4 b0 = *(const float4*)&Bs[kk][tx * 8];
            float4 b1 = *(const float4*)&Bs[kk][tx * 8 + 4];
            float ar[8] = {a0.x, a0.y, a0.z, a0.w, a1.x, a1.y, a1.z, a1.w};
            float br[8] = {b0.x, b0.y, b0.z, b0.w, b1.x, b1.y, b1.z, b1.w};
            #pragma unroll
            for (int i = 0; i < 8; i++)
                #pragma unroll
                for (int j = 0; j < 8; j++)
                    acc[i][j] += ar[i] * br[j];
        }
    }

    #pragma unroll
    for (int i = 0; i < 8; i++) {
        const int row = bm + ty * 8 + i;
        #pragma unroll
        for (int j = 0; j < 8; j += 4) {
            const int col = bn + tx * 8 + j;
            float4 outv;
            outv.x = acc[i][j + 0] + bias[col + 0];
            outv.y = acc[i][j + 1] + bias[col + 1];
            outv.z = acc[i][j + 2] + bias[col + 2];
            outv.w = acc[i][j + 3] + bias[col + 3];
            *(float4*)&C[(size_t)row * N + col] = outv;
        }
    }
}

// ---------------------------------------------------------------------------
// Flash attention, fp32. One block = 64 query rows of one (b,h).
// One thread per query row: q[64] and o[64] in registers.
// qkv layout: [B,S,3E]; for (b,s,h): Q at h*192+0, K at +64, V at +128.
// ---------------------------------------------------------------------------
__global__ __launch_bounds__(64)
void flash_attn_kernel()
{
    __shared__ float Ks[64][64];
    __shared__ float Vs[64][64];
    __shared__ float Ss[64][65];   // padded pitch -> conflict-free own-row access

    const int r  = threadIdx.x;
    const int qt = blockIdx.x;
    const int h  = blockIdx.y;
    const int b  = blockIdx.z;
    const int sq = qt * 64 + r;

    const float* qrow = g_qkv + (size_t)(b * S_ + sq) * TE_ + h * (3 * D_);
    float4 q[16];
    #pragma unroll
    for (int j = 0; j < 16; j++) {
        float4 v = *(const float4*)(qrow + j * 4);
        v.x *= 0.125f; v.y *= 0.125f; v.z *= 0.125f; v.w *= 0.125f; // 1/sqrt(64)
        q[j] = v;
    }

    float o[64];
    #pragma unroll
    for (int d = 0; d < 64; d++) o[d] = 0.f;
    float m = -1e30f, l = 0.f;

    for (int kt = 0; kt < S_ / 64; kt++) {
        const float* kvbase = g_qkv + (size_t)(b * S_ + kt * 64) * TE_ + h * (3 * D_);
        // cooperative K/V tile load (each i = one float4 of one row)
        for (int i = r; i < 64 * 16; i += 64) {
            const int kn = i >> 4;
            const int d4 = (i & 15) << 2;
            const float* p = kvbase + (size_t)kn * TE_ + d4;
            *(float4*)&Ks[kn][d4] = *(const float4*)(p + D_);
            *(float4*)&Vs[kn][d4] = *(const float4*)(p + 2 * D_);
        }
        __syncthreads();

        // pass 1: scores for this thread's row (Ks broadcast reads)
        float rowmax = -1e30f;
        #pragma unroll 4
        for (int kn = 0; kn < 64; kn++) {
            float s = 0.f;
            #pragma unroll
            for (int j = 0; j < 16; j++) {
                float4 kv = *(const float4*)&Ks[kn][j * 4];
                s += q[j].x * kv.x + q[j].y * kv.y + q[j].z * kv.z + q[j].w * kv.w;
            }
            Ss[r][kn] = s;
            rowmax = fmaxf(rowmax, s);
        }

        const float m_new = fmaxf(m, rowmax);
        const float scale = __expf(m - m_new);
        l *= scale;
        #pragma unroll
        for (int d = 0; d < 64; d++) o[d] *= scale;

        // pass 2: softmax weights + PV accumulation (Vs broadcast reads)
        #pragma unroll 2
        for (int kn = 0; kn < 64; kn++) {
            const float p = __expf(Ss[r][kn] - m_new);
            l += p;
            #pragma unroll
            for (int j = 0; j < 16; j++) {
                float4 vv = *(const float4*)&Vs[kn][j * 4];
                o[j * 4 + 0] += p * vv.x;
                o[j * 4 + 1] += p * vv.y;
                o[j * 4 + 2] += p * vv.z;
                o[j * 4 + 3] += p * vv.w;
            }
        }
        m = m_new;
        __syncthreads();
    }

    const float inv = 1.f / l;
    float* outp = g_vals + (size_t)(b * S_ + sq) * E_ + h * D_;
    #pragma unroll
    for (int j = 0; j < 16; j++) {
        float4 v;
        v.x = o[j * 4 + 0] * inv;
        v.y = o[j * 4 + 1] * inv;
        v.z = o[j * 4 + 2] * inv;
        v.w = o[j * 4 + 3] * inv;
        *(float4*)(outp + j * 4) = v;
    }
}

// ---------------------------------------------------------------------------
// Launch: qkv = x @ w_qkv^T + b_qkv ; flash attention ; out = vals @ w_o^T + b_o
// ---------------------------------------------------------------------------
extern "C" void kernel_launch(void* const* d_in, const int* in_sizes, int n_in,
                              void* d_out, int out_size)
{
    const float* x     = (const float*)d_in[0];
    const float* w_qkv = (const float*)d_in[1];
    const float* b_qkv = (const float*)d_in[2];
    const float* w_o   = (const float*)d_in[3];
    const float* b_o   = (const float*)d_in[4];
    float* out = (float*)d_out;

    float* qkv  = nullptr;
    float* vals = nullptr;
    cudaGetSymbolAddress((void**)&qkv,  g_qkv);
    cudaGetSymbolAddress((void**)&vals, g_vals);

    dim3 g1(TE_ / 128, MTOT / 128);     // 24 x 32
    sgemm_nt_bias<<<g1, 256>>>(x, w_qkv, b_qkv, qkv, MTOT, TE_, E_);

    dim3 g2(S_ / 64, H_, B_);           // 32 x 16 x 2
    flash_attn_kernel<<<g2, 64>>>();

    dim3 g3(E_ / 128, MTOT / 128);      // 8 x 32
    sgemm_nt_bias<<<g3, 256>>>(vals, w_o, b_o, out, MTOT, E_, E_);
}

// round 3
// speedup vs baseline: 6.4562x; 6.4562x over previous
#include <cuda_runtime.h>
#include <cuda_bf16.h>
#include <cstdint>

#define B_   2
#define S_   2048
#define H_   16
#define D_   64
#define E_   1024
#define TE_  3072
#define MTOT (B_ * S_)   // 4096

// ---------------------------------------------------------------------------
// Scratch (__device__ globals; no allocation allowed)
// ---------------------------------------------------------------------------
__device__ float g_qkv[(size_t)MTOT * TE_];
__device__ float g_vals[(size_t)MTOT * E_];
__device__ __nv_bfloat16 g_x_hi[(size_t)MTOT * E_];
__device__ __nv_bfloat16 g_x_lo[(size_t)MTOT * E_];
__device__ __nv_bfloat16 g_wq_hi[(size_t)TE_ * E_];
__device__ __nv_bfloat16 g_wq_lo[(size_t)TE_ * E_];
__device__ __nv_bfloat16 g_wo_hi[(size_t)E_ * E_];
__device__ __nv_bfloat16 g_wo_lo[(size_t)E_ * E_];
__device__ __nv_bfloat16 g_v_hi[(size_t)MTOT * E_];
__device__ __nv_bfloat16 g_v_lo[(size_t)MTOT * E_];

// ---------------------------------------------------------------------------
// Helpers (all sm_80-level PTX: safe under plain compute_103 target)
// ---------------------------------------------------------------------------
__device__ __forceinline__ uint32_t smem_u32(const void* p) {
    uint32_t a;
    asm("{ .reg .u64 t; cvta.to.shared.u64 t, %1; cvt.u32.u64 %0, t; }" : "=r"(a) : "l"(p));
    return a;
}
__device__ __forceinline__ uint32_t pk2(float a, float b) {
    __nv_bfloat162 t = __floats2bfloat162_rn(a, b);   // .x = a (low), .y = b (high)
    return *reinterpret_cast<uint32_t*>(&t);
}
__device__ __forceinline__ uint32_t pkh(__nv_bfloat16 a, __nv_bfloat16 b) {
    __nv_bfloat162 t(a, b);
    return *reinterpret_cast<uint32_t*>(&t);
}
__device__ __forceinline__ void ldm_x4(uint32_t* r, uint32_t addr) {
    asm volatile("ldmatrix.sync.aligned.m8n8.x4.shared.b16 {%0,%1,%2,%3}, [%4];"
                 : "=r"(r[0]), "=r"(r[1]), "=r"(r[2]), "=r"(r[3]) : "r"(addr));
}
__device__ __forceinline__ void ldm_x2(uint32_t* r, uint32_t addr) {
    asm volatile("ldmatrix.sync.aligned.m8n8.x2.shared.b16 {%0,%1}, [%2];"
                 : "=r"(r[0]), "=r"(r[1]) : "r"(addr));
}
__device__ __forceinline__ void ldm_x2t(uint32_t* r, uint32_t addr) {
    asm volatile("ldmatrix.sync.aligned.m8n8.x2.trans.shared.b16 {%0,%1}, [%2];"
                 : "=r"(r[0]), "=r"(r[1]) : "r"(addr));
}
__device__ __forceinline__ void mma16816(float* c, const uint32_t* a, const uint32_t* b) {
    asm volatile(
        "mma.sync.aligned.m16n8k16.row.col.f32.bf16.bf16.f32 "
        "{%0,%1,%2,%3}, {%4,%5,%6,%7}, {%8,%9}, {%0,%1,%2,%3};"
        : "+f"(c[0]), "+f"(c[1]), "+f"(c[2]), "+f"(c[3])
        : "r"(a[0]), "r"(a[1]), "r"(a[2]), "r"(a[3]), "r"(b[0]), "r"(b[1]));
}
__device__ __forceinline__ void cp_async16(uint32_t saddr, const void* gaddr) {
    asm volatile("cp.async.cg.shared.global [%0], [%1], 16;" :: "r"(saddr), "l"(gaddr) : "memory");
}
__device__ __forceinline__ void cp_commit() {
    asm volatile("cp.async.commit_group;" ::: "memory");
}
__device__ __forceinline__ void cp_wait0() {
    asm volatile("cp.async.wait_group 0;" ::: "memory");
}

// ---------------------------------------------------------------------------
// fp32 -> bf16 hi + bf16 lo split
// ---------------------------------------------------------------------------
__global__ __launch_bounds__(256)
void split_bf16x2(const float* __restrict__ in, __nv_bfloat16* __restrict__ hi,
                  __nv_bfloat16* __restrict__ lo, int n4)
{
    int i = blockIdx.x * blockDim.x + threadIdx.x;
    if (i >= n4) return;
    float4 v = ((const float4*)in)[i];
    __nv_bfloat16 h0 = __float2bfloat16_rn(v.x);
    __nv_bfloat16 h1 = __float2bfloat16_rn(v.y);
    __nv_bfloat16 h2 = __float2bfloat16_rn(v.z);
    __nv_bfloat16 h3 = __float2bfloat16_rn(v.w);
    __nv_bfloat16 l0 = __float2bfloat16_rn(v.x - __bfloat162float(h0));
    __nv_bfloat16 l1 = __float2bfloat16_rn(v.y - __bfloat162float(h1));
    __nv_bfloat16 l2 = __float2bfloat16_rn(v.z - __bfloat162float(h2));
    __nv_bfloat16 l3 = __float2bfloat16_rn(v.w - __bfloat162float(h3));
    uint2 hp = make_uint2(pkh(h0, h1), pkh(h2, h3));
    uint2 lp = make_uint2(pkh(l0, l1), pkh(l2, l3));
    *(uint2*)(hi + (size_t)i * 4) = hp;
    *(uint2*)(lo + (size_t)i * 4) = lp;
}

// ---------------------------------------------------------------------------
// HMMA split-bf16 GEMM (NT): C[M,N] = A[M,K]*B[N,K]^T + bias[N]
// 128x128 tile, 8 warps (warp tile 64x32), BK=32, cp.async double buffer.
// smem stage: tiles [Ah | Al | Bh | Bl], each 128 rows x 64B, XOR swizzle.
// ---------------------------------------------------------------------------
#define GT_BYTES   8192           // one tile: 128*64
#define GSTAGE     (4 * GT_BYTES) // 32768
#define GSMEM      (2 * GSTAGE)   // 65536

__device__ __forceinline__ uint32_t gsw(uint32_t row, uint32_t kg) {
    return row * 64u + ((kg ^ ((row >> 1) & 3u)) << 4);
}

__global__ __launch_bounds__(256, 1)
void gemm_mma(const __nv_bfloat16* __restrict__ Ah, const __nv_bfloat16* __restrict__ Al,
              const __nv_bfloat16* __restrict__ Bh, const __nv_bfloat16* __restrict__ Bl,
              const float* __restrict__ bias, float* __restrict__ C, int N, int K)
{
    extern __shared__ char smem[];
    const uint32_t sb = smem_u32(smem);
    const int t = threadIdx.x;
    const int wid = t >> 5;
    const int lane = t & 31;
    const int bm = blockIdx.y * 128;
    const int bn = blockIdx.x * 128;
    const int wm = (wid >> 2) * 64;     // 0 or 64
    const int wn = (wid & 3) * 32;      // 0..96

    // per-thread cp.async mapping: 8 slots; slot = i*256 + t
    const __nv_bfloat16* gt[4] = {Ah, Al, Bh, Bl};
    const char* gptr[8];
    uint32_t soff[8];
    #pragma unroll
    for (int i = 0; i < 8; i++) {
        int s = i * 256 + t;            // 0..2047
        int tile = s >> 9;              // 0..3
        int row = (s >> 2) & 127;
        int kg = s & 3;
        int grow = (tile < 2 ? bm : bn) + row;
        gptr[i] = (const char*)(gt[tile] + (size_t)grow * K) + kg * 16;
        soff[i] = (uint32_t)tile * GT_BYTES + gsw(row, kg);
    }

    float acc[4][4][4];
    #pragma unroll
    for (int mt = 0; mt < 4; mt++)
        #pragma unroll
        for (int nt = 0; nt < 4; nt++)
            #pragma unroll
            for (int j = 0; j < 4; j++) acc[mt][nt][j] = 0.f;

    const int niter = K >> 5;   // K/32

    // prologue: stage 0
    #pragma unroll
    for (int i = 0; i < 8; i++) cp_async16(sb + soff[i], gptr[i]);
    cp_commit();

    for (int c = 0; c < niter; c++) {
        cp_wait0();
        __syncthreads();

        if (c + 1 < niter) {
            const uint32_t dst = sb + ((c + 1) & 1) * GSTAGE;
            const int koff = (c + 1) * 64;   // 32 bf16 = 64 bytes
            #pragma unroll
            for (int i = 0; i < 8; i++) cp_async16(dst + soff[i], gptr[i] + koff);
            cp_commit();
        }

        const uint32_t stage = sb + (c & 1) * GSTAGE;
        #pragma unroll
        for (int ks = 0; ks < 2; ks++) {
            uint32_t ah[4][4], al[4][4], bh[4][2], bl[4][2];
            #pragma unroll
            for (int mt = 0; mt < 4; mt++) {
                uint32_t row = wm + mt * 16 + (lane & 15);
                uint32_t kg = ks * 2 + (lane >> 4);
                uint32_t off = gsw(row, kg);
                ldm_x4(ah[mt], stage + off);
                ldm_x4(al[mt], stage + GT_BYTES + off);
            }
            #pragma unroll
            for (int nt = 0; nt < 4; nt++) {
                uint32_t row = wn + nt * 8 + (lane & 7);
                uint32_t kg = ks * 2 + ((lane >> 3) & 1);
                uint32_t off = gsw(row, kg);
                ldm_x2(bh[nt], stage + 2 * GT_BYTES + off);
                ldm_x2(bl[nt], stage + 3 * GT_BYTES + off);
            }
            #pragma unroll
            for (int mt = 0; mt < 4; mt++)
                #pragma unroll
                for (int nt = 0; nt < 4; nt++) {
                    mma16816(acc[mt][nt], ah[mt], bh[nt]);
                    mma16816(acc[mt][nt], ah[mt], bl[nt]);
                    mma16816(acc[mt][nt], al[mt], bh[nt]);
                }
        }
    }

    // epilogue
    #pragma unroll
    for (int mt = 0; mt < 4; mt++) {
        const int r0 = bm + wm + mt * 16 + (lane >> 2);
        #pragma unroll
        for (int nt = 0; nt < 4; nt++) {
            const int col = bn + wn + nt * 8 + (lane & 3) * 2;
            float b0 = bias[col], b1 = bias[col + 1];
            float2 v0 = make_float2(acc[mt][nt][0] + b0, acc[mt][nt][1] + b1);
            float2 v1 = make_float2(acc[mt][nt][2] + b0, acc[mt][nt][3] + b1);
            *(float2*)&C[(size_t)r0 * N + col] = v0;
            *(float2*)&C[(size_t)(r0 + 8) * N + col] = v1;
        }
    }
}

// ---------------------------------------------------------------------------
// HMMA flash attention. CTA = 64 q-rows of one (b,h), 4 warps (16 rows each).
// smem: Qh Ql Kh Kl Vh Vl, each [64][64] bf16, 128B rows, XOR swizzle.
// ---------------------------------------------------------------------------
#define FT_BYTES 8192
#define FSMEM    (6 * FT_BYTES)   // 49152

__device__ __forceinline__ uint32_t fsw(uint32_t row, uint32_t kg) {
    return row * 128u + ((kg ^ (row & 7u)) << 4);
}

__global__ __launch_bounds__(128)
void flash_mma()
{
    extern __shared__ char smem[];
    const uint32_t sb = smem_u32(smem);
    const uint32_t sQh = sb, sQl = sb + FT_BYTES;
    const uint32_t sKh = sb + 2 * FT_BYTES, sKl = sb + 3 * FT_BYTES;
    const uint32_t sVh = sb + 4 * FT_BYTES, sVl = sb + 5 * FT_BYTES;

    const int t = threadIdx.x;
    const int wid = t >> 5;
    const int lane = t & 31;
    const int qt = blockIdx.x, h = blockIdx.y, b = blockIdx.z;

    // ---- load Q (scaled by 1/sqrt(D)), split hi/lo into smem ----
    {
        const float* qbase = g_qkv + (size_t)(b * S_ + qt * 64) * TE_ + h * (3 * D_);
        #pragma unroll
        for (int i = 0; i < 4; i++) {
            int s = i * 128 + t;        // 0..511
            int row = s >> 3, kg = s & 7;
            const float* p = qbase + (size_t)row * TE_ + kg * 8;
            float4 v0 = *(const float4*)p;
            float4 v1 = *(const float4*)(p + 4);
            float f[8] = {v0.x, v0.y, v0.z, v0.w, v1.x, v1.y, v1.z, v1.w};
            uint32_t hp[4], lp[4];
            #pragma unroll
            for (int j = 0; j < 4; j++) {
                float a = f[2 * j] * 0.125f, c = f[2 * j + 1] * 0.125f;
                __nv_bfloat16 ha = __float2bfloat16_rn(a), hc = __float2bfloat16_rn(c);
                hp[j] = pkh(ha, hc);
                lp[j] = pk2(a - __bfloat162float(ha), c - __bfloat162float(hc));
            }
            uint32_t off = fsw(row, kg);
            *(uint4*)(smem + (sQh - sb) + off) = make_uint4(hp[0], hp[1], hp[2], hp[3]);
            *(uint4*)(smem + (sQl - sb) + off) = make_uint4(lp[0], lp[1], lp[2], lp[3]);
        }
    }
    __syncthreads();

    // ---- Q fragments (persistent): 4 ksteps x 4 regs, hi and lo ----
    uint32_t aqh[4][4], aql[4][4];
    #pragma unroll
    for (int ks = 0; ks < 4; ks++) {
        uint32_t row = wid * 16 + (lane & 15);
        uint32_t kg = ks * 2 + (lane >> 4);
        uint32_t off = fsw(row, kg);
        ldm_x4(aqh[ks], sQh + off);
        ldm_x4(aql[ks], sQl + off);
    }

    float o[8][4];
    #pragma unroll
    for (int nt = 0; nt < 8; nt++)
        #pragma unroll
        for (int j = 0; j < 4; j++) o[nt][j] = 0.f;
    float m0 = -1e30f, m1 = -1e30f, l0 = 0.f, l1 = 0.f;

    for (int kt = 0; kt < S_ / 64; kt++) {
        __syncthreads();   // previous tile's mma reads complete
        // ---- load K,V tile, split hi/lo ----
        {
            const float* kvb = g_qkv + (size_t)(b * S_ + kt * 64) * TE_ + h * (3 * D_);
            #pragma unroll
            for (int i = 0; i < 4; i++) {
                int s = i * 128 + t;
                int row = s >> 3, kg = s & 7;
                const float* kp = kvb + (size_t)row * TE_ + D_ + kg * 8;
                const float* vp = kvb + (size_t)row * TE_ + 2 * D_ + kg * 8;
                uint32_t off = fsw(row, kg);
                {
                    float4 v0 = *(const float4*)kp;
                    float4 v1 = *(const float4*)(kp + 4);
                    float f[8] = {v0.x, v0.y, v0.z, v0.w, v1.x, v1.y, v1.z, v1.w};
                    uint32_t hp[4], lp[4];
                    #pragma unroll
                    for (int j = 0; j < 4; j++) {
                        __nv_bfloat16 ha = __float2bfloat16_rn(f[2 * j]);
                        __nv_bfloat16 hc = __float2bfloat16_rn(f[2 * j + 1]);
                        hp[j] = pkh(ha, hc);
                        lp[j] = pk2(f[2 * j] - __bfloat162float(ha),
                                    f[2 * j + 1] - __bfloat162float(hc));
                    }
                    *(uint4*)(smem + (sKh - sb) + off) = make_uint4(hp[0], hp[1], hp[2], hp[3]);
                    *(uint4*)(smem + (sKl - sb) + off) = make_uint4(lp[0], lp[1], lp[2], lp[3]);
                }
                {
                    float4 v0 = *(const float4*)vp;
                    float4 v1 = *(const float4*)(vp + 4);
                    float f[8] = {v0.x, v0.y, v0.z, v0.w, v1.x, v1.y, v1.z, v1.w};
                    uint32_t hp[4], lp[4];
                    #pragma unroll
                    for (int j = 0; j < 4; j++) {
                        __nv_bfloat16 ha = __float2bfloat16_rn(f[2 * j]);
                        __nv_bfloat16 hc = __float2bfloat16_rn(f[2 * j + 1]);
                        hp[j] = pkh(ha, hc);
                        lp[j] = pk2(f[2 * j] - __bfloat162float(ha),
                                    f[2 * j + 1] - __bfloat162float(hc));
                    }
                    *(uint4*)(smem + (sVh - sb) + off) = make_uint4(hp[0], hp[1], hp[2], hp[3]);
                    *(uint4*)(smem + (sVl - sb) + off) = make_uint4(lp[0], lp[1], lp[2], lp[3]);
                }
            }
        }
        __syncthreads();

        // ---- S = Q K^T (split 3-term, fp32 accum) ----
        float sc[8][4];
        #pragma unroll
        for (int nt = 0; nt < 8; nt++)
            #pragma unroll
            for (int j = 0; j < 4; j++) sc[nt][j] = 0.f;
        #pragma unroll
        for (int ks = 0; ks < 4; ks++) {
            #pragma unroll
            for (int nt = 0; nt < 8; nt++) {
                uint32_t row = nt * 8 + (lane & 7);
                uint32_t kg = ks * 2 + ((lane >> 3) & 1);
                uint32_t off = fsw(row, kg);
                uint32_t bh[2], bl[2];
                ldm_x2(bh, sKh + off);
                ldm_x2(bl, sKl + off);
                mma16816(sc[nt], aqh[ks], bh);
                mma16816(sc[nt], aqh[ks], bl);
                mma16816(sc[nt], aql[ks], bh);
            }
        }

        // ---- online softmax (rows r=lane/4 and r+8 within warp tile) ----
        float rx0 = -1e30f, rx1 = -1e30f;
        #pragma unroll
        for (int nt = 0; nt < 8; nt++) {
            rx0 = fmaxf(rx0, fmaxf(sc[nt][0], sc[nt][1]));
            rx1 = fmaxf(rx1, fmaxf(sc[nt][2], sc[nt][3]));
        }
        rx0 = fmaxf(rx0, __shfl_xor_sync(0xffffffffu, rx0, 1));
        rx0 = fmaxf(rx0, __shfl_xor_sync(0xffffffffu, rx0, 2));
        rx1 = fmaxf(rx1, __shfl_xor_sync(0xffffffffu, rx1, 1));
        rx1 = fmaxf(rx1, __shfl_xor_sync(0xffffffffu, rx1, 2));

        const float mn0 = fmaxf(m0, rx0), mn1 = fmaxf(m1, rx1);
        const float s0 = __expf(m0 - mn0), s1 = __expf(m1 - mn1);
        m0 = mn0; m1 = mn1;
        #pragma unroll
        for (int nt = 0; nt < 8; nt++) {
            o[nt][0] *= s0; o[nt][1] *= s0;
            o[nt][2] *= s1; o[nt][3] *= s1;
        }
        float sum0 = 0.f, sum1 = 0.f;
        #pragma unroll
        for (int nt = 0; nt < 8; nt++) {
            sc[nt][0] = __expf(sc[nt][0] - mn0);
            sc[nt][1] = __expf(sc[nt][1] - mn0);
            sc[nt][2] = __expf(sc[nt][2] - mn1);
            sc[nt][3] = __expf(sc[nt][3] - mn1);
            sum0 += sc[nt][0] + sc[nt][1];
            sum1 += sc[nt][2] + sc[nt][3];
        }
        sum0 += __shfl_xor_sync(0xffffffffu, sum0, 1);
        sum0 += __shfl_xor_sync(0xffffffffu, sum0, 2);
        sum1 += __shfl_xor_sync(0xffffffffu, sum1, 1);
        sum1 += __shfl_xor_sync(0xffffffffu, sum1, 2);
        l0 = l0 * s0 + sum0;
        l1 = l1 * s1 + sum1;

        // ---- O += P V (split 3-term; P frags straight from registers) ----
        #pragma unroll
        for (int ks = 0; ks < 4; ks++) {
            uint32_t aph[4], apl[4];
            {
                const int j0 = 2 * ks, j1 = 2 * ks + 1;
                __nv_bfloat16 h00 = __float2bfloat16_rn(sc[j0][0]);
                __nv_bfloat16 h01 = __float2bfloat16_rn(sc[j0][1]);
                __nv_bfloat16 h02 = __float2bfloat16_rn(sc[j0][2]);
                __nv_bfloat16 h03 = __float2bfloat16_rn(sc[j0][3]);
                __nv_bfloat16 h10 = __float2bfloat16_rn(sc[j1][0]);
                __nv_bfloat16 h11 = __float2bfloat16_rn(sc[j1][1]);
                __nv_bfloat16 h12 = __float2bfloat16_rn(sc[j1][2]);
                __nv_bfloat16 h13 = __float2bfloat16_rn(sc[j1][3]);
                aph[0] = pkh(h00, h01);
                aph[1] = pkh(h02, h03);
                aph[2] = pkh(h10, h11);
                aph[3] = pkh(h12, h13);
                apl[0] = pk2(sc[j0][0] - __bfloat162float(h00), sc[j0][1] - __bfloat162float(h01));
                apl[1] = pk2(sc[j0][2] - __bfloat162float(h02), sc[j0][3] - __bfloat162float(h03));
                apl[2] = pk2(sc[j1][0] - __bfloat162float(h10), sc[j1][1] - __bfloat162float(h11));
                apl[3] = pk2(sc[j1][2] - __bfloat162float(h12), sc[j1][3] - __bfloat162float(h13));
            }
            #pragma unroll
            for (int nt = 0; nt < 8; nt++) {
                uint32_t row = ks * 16 + (lane & 15);      // key index
                uint32_t off = fsw(row, nt);
                uint32_t bh[2], bl[2];
                ldm_x2t(bh, sVh + off);
                ldm_x2t(bl, sVl + off);
                mma16816(o[nt], aph, bh);
                mma16816(o[nt], aph, bl);
                mma16816(o[nt], apl, bh);
            }
        }
    }

    // ---- normalize and store ----
    const float inv0 = 1.f / l0, inv1 = 1.f / l1;
    const int r0 = qt * 64 + wid * 16 + (lane >> 2);
    float* ob0 = g_vals + (size_t)(b * S_ + r0) * E_ + h * D_;
    float* ob1 = g_vals + (size_t)(b * S_ + r0 + 8) * E_ + h * D_;
    #pragma unroll
    for (int nt = 0; nt < 8; nt++) {
        const int col = nt * 8 + (lane & 3) * 2;
        *(float2*)(ob0 + col) = make_float2(o[nt][0] * inv0, o[nt][1] * inv0);
        *(float2*)(ob1 + col) = make_float2(o[nt][2] * inv1, o[nt][3] * inv1);
    }
}

// ---------------------------------------------------------------------------
// Launch
// ---------------------------------------------------------------------------
extern "C" void kernel_launch(void* const* d_in, const int* in_sizes, int n_in,
                              void* d_out, int out_size)
{
    const float* x     = (const float*)d_in[0];
    const float* w_qkv = (const float*)d_in[1];
    const float* b_qkv = (const float*)d_in[2];
    const float* w_o   = (const float*)d_in[3];
    const float* b_o   = (const float*)d_in[4];
    float* out = (float*)d_out;

    float *qkv, *vals;
    __nv_bfloat16 *x_hi, *x_lo, *wq_hi, *wq_lo, *wo_hi, *wo_lo, *v_hi, *v_lo;
    cudaGetSymbolAddress((void**)&qkv,  g_qkv);
    cudaGetSymbolAddress((void**)&vals, g_vals);
    cudaGetSymbolAddress((void**)&x_hi, g_x_hi);
    cudaGetSymbolAddress((void**)&x_lo, g_x_lo);
    cudaGetSymbolAddress((void**)&wq_hi, g_wq_hi);
    cudaGetSymbolAddress((void**)&wq_lo, g_wq_lo);
    cudaGetSymbolAddress((void**)&wo_hi, g_wo_hi);
    cudaGetSymbolAddress((void**)&wo_lo, g_wo_lo);
    cudaGetSymbolAddress((void**)&v_hi, g_v_hi);
    cudaGetSymbolAddress((void**)&v_lo, g_v_lo);

    cudaFuncSetAttribute(gemm_mma, cudaFuncAttributeMaxDynamicSharedMemorySize, GSMEM);
    cudaFuncSetAttribute(flash_mma, cudaFuncAttributeMaxDynamicSharedMemorySize, FSMEM);

    {
        int n4 = (MTOT * E_) / 4;
        split_bf16x2<<<(n4 + 255) / 256, 256>>>(x, x_hi, x_lo, n4);
        n4 = (TE_ * E_) / 4;
        split_bf16x2<<<(n4 + 255) / 256, 256>>>(w_qkv, wq_hi, wq_lo, n4);
        n4 = (E_ * E_) / 4;
        split_bf16x2<<<(n4 + 255) / 256, 256>>>(w_o, wo_hi, wo_lo, n4);
    }

    {
        dim3 g(TE_ / 128, MTOT / 128);   // 24 x 32
        gemm_mma<<<g, 256, GSMEM>>>(x_hi, x_lo, wq_hi, wq_lo, b_qkv, qkv, TE_, E_);
    }

    {
        dim3 g(S_ / 64, H_, B_);          // 32 x 16 x 2
        flash_mma<<<g, 128, FSMEM>>>();
    }

    {
        int n4 = (MTOT * E_) / 4;
        split_bf16x2<<<(n4 + 255) / 256, 256>>>(vals, v_hi, v_lo, n4);
        dim3 g(E_ / 128, MTOT / 128);     // 8 x 32
        gemm_mma<<<g, 256, GSMEM>>>(v_hi, v_lo, wo_hi, wo_lo, b_o, out, E_, E_);
    }
}

// round 4
// speedup vs baseline: 7.8146x; 1.2104x over previous
#include <cuda_runtime.h>
#include <cuda_bf16.h>
#include <cstdint>

#define B_   2
#define S_   2048
#define H_   16
#define D_   64
#define E_   1024
#define TE_  3072
#define MTOT (B_ * S_)   // 4096

// ---------------------------------------------------------------------------
// Scratch (__device__ globals; no allocation allowed)
// ---------------------------------------------------------------------------
__device__ __nv_bfloat16 g_qkv_hi[(size_t)MTOT * TE_];
__device__ __nv_bfloat16 g_qkv_lo[(size_t)MTOT * TE_];
__device__ __nv_bfloat16 g_o_hi[(size_t)MTOT * E_];
__device__ __nv_bfloat16 g_o_lo[(size_t)MTOT * E_];
__device__ __nv_bfloat16 g_x_hi[(size_t)MTOT * E_];
__device__ __nv_bfloat16 g_x_lo[(size_t)MTOT * E_];
__device__ __nv_bfloat16 g_wq_hi[(size_t)TE_ * E_];
__device__ __nv_bfloat16 g_wq_lo[(size_t)TE_ * E_];
__device__ __nv_bfloat16 g_wo_hi[(size_t)E_ * E_];
__device__ __nv_bfloat16 g_wo_lo[(size_t)E_ * E_];

// ---------------------------------------------------------------------------
// Helpers (sm_80-level PTX only: safe under plain compute_103 target)
// ---------------------------------------------------------------------------
__device__ __forceinline__ uint32_t smem_u32(const void* p) {
    uint32_t a;
    asm("{ .reg .u64 t; cvta.to.shared.u64 t, %1; cvt.u32.u64 %0, t; }" : "=r"(a) : "l"(p));
    return a;
}
__device__ __forceinline__ uint32_t pk2(float a, float b) {
    __nv_bfloat162 t = __floats2bfloat162_rn(a, b);
    return *reinterpret_cast<uint32_t*>(&t);
}
__device__ __forceinline__ uint32_t pkh(__nv_bfloat16 a, __nv_bfloat16 b) {
    __nv_bfloat162 t(a, b);
    return *reinterpret_cast<uint32_t*>(&t);
}
__device__ __forceinline__ void ldm_x4(uint32_t* r, uint32_t addr) {
    asm volatile("ldmatrix.sync.aligned.m8n8.x4.shared.b16 {%0,%1,%2,%3}, [%4];"
                 : "=r"(r[0]), "=r"(r[1]), "=r"(r[2]), "=r"(r[3]) : "r"(addr));
}
__device__ __forceinline__ void ldm_x2(uint32_t* r, uint32_t addr) {
    asm volatile("ldmatrix.sync.aligned.m8n8.x2.shared.b16 {%0,%1}, [%2];"
                 : "=r"(r[0]), "=r"(r[1]) : "r"(addr));
}
__device__ __forceinline__ void ldm_x2t(uint32_t* r, uint32_t addr) {
    asm volatile("ldmatrix.sync.aligned.m8n8.x2.trans.shared.b16 {%0,%1}, [%2];"
                 : "=r"(r[0]), "=r"(r[1]) : "r"(addr));
}
__device__ __forceinline__ void mma16816(float* c, const uint32_t* a, const uint32_t* b) {
    asm volatile(
        "mma.sync.aligned.m16n8k16.row.col.f32.bf16.bf16.f32 "
        "{%0,%1,%2,%3}, {%4,%5,%6,%7}, {%8,%9}, {%0,%1,%2,%3};"
        : "+f"(c[0]), "+f"(c[1]), "+f"(c[2]), "+f"(c[3])
        : "r"(a[0]), "r"(a[1]), "r"(a[2]), "r"(a[3]), "r"(b[0]), "r"(b[1]));
}
__device__ __forceinline__ void cp_async16(uint32_t saddr, const void* gaddr) {
    asm volatile("cp.async.cg.shared.global [%0], [%1], 16;" :: "r"(saddr), "l"(gaddr) : "memory");
}
__device__ __forceinline__ void cp_commit() {
    asm volatile("cp.async.commit_group;" ::: "memory");
}
#define CP_WAIT(n) asm volatile("cp.async.wait_group %0;" :: "n"(n) : "memory")

// 128B-row XOR swizzle (8x16B groups), conflict-free for ldmatrix
__device__ __forceinline__ uint32_t sw128(uint32_t row, uint32_t kg) {
    return row * 128u + ((kg ^ (row & 7u)) << 4);
}

// ---------------------------------------------------------------------------
// fp32 -> bf16 hi + bf16 lo split
// ---------------------------------------------------------------------------
__global__ __launch_bounds__(256)
void split_bf16x2(const float* __restrict__ in, __nv_bfloat16* __restrict__ hi,
                  __nv_bfloat16* __restrict__ lo, int n4)
{
    int i = blockIdx.x * blockDim.x + threadIdx.x;
    if (i >= n4) return;
    float4 v = ((const float4*)in)[i];
    __nv_bfloat16 h0 = __float2bfloat16_rn(v.x);
    __nv_bfloat16 h1 = __float2bfloat16_rn(v.y);
    __nv_bfloat16 h2 = __float2bfloat16_rn(v.z);
    __nv_bfloat16 h3 = __float2bfloat16_rn(v.w);
    uint2 hp = make_uint2(pkh(h0, h1), pkh(h2, h3));
    uint2 lp = make_uint2(pk2(v.x - __bfloat162float(h0), v.y - __bfloat162float(h1)),
                          pk2(v.z - __bfloat162float(h2), v.w - __bfloat162float(h3)));
    *(uint2*)(hi + (size_t)i * 4) = hp;
    *(uint2*)(lo + (size_t)i * 4) = lp;
}

// ---------------------------------------------------------------------------
// HMMA split-bf16 GEMM (NT): C = A[M,K]*B[N,K]^T + bias
// 128x128 tile, 8 warps (64x32 each), BK=64, 2-stage cp.async pipeline.
// MODE 0: write fp32 C.  MODE 1: write bf16 hi/lo split (Chi/Clo).
// ---------------------------------------------------------------------------
#define GT2     16384                 // one tile: 128 rows x 128B
#define GSTAGE2 (4 * GT2)             // Ah Al Bh Bl
#define GSMEM2  (2 * GSTAGE2)         // 131072

__device__ __forceinline__ void gemm_issue(
    uint32_t sdst, const __nv_bfloat16* Ah, const __nv_bfloat16* Al,
    const __nv_bfloat16* Bh, const __nv_bfloat16* Bl,
    int bm, int bn, int K, int t, int c)
{
    #pragma unroll
    for (int i = 0; i < 16; i++) {
        const int tile = i >> 2;                  // 0..3
        const int row = (i & 3) * 32 + (t >> 3);  // 0..127
        const int kg = t & 7;
        const __nv_bfloat16* base = (tile == 0) ? Ah : (tile == 1) ? Al
                                  : (tile == 2) ? Bh : Bl;
        const int grow = (tile < 2 ? bm : bn) + row;
        const char* g = (const char*)(base + (size_t)grow * K) + kg * 16 + c * 128;
        cp_async16(sdst + (uint32_t)tile * GT2 + sw128(row, kg), g);
    }
    cp_commit();
}

template <int MODE>
__global__ __launch_bounds__(256, 1)
void gemm_mma(const __nv_bfloat16* __restrict__ Ah, const __nv_bfloat16* __restrict__ Al,
              const __nv_bfloat16* __restrict__ Bh, const __nv_bfloat16* __restrict__ Bl,
              const float* __restrict__ bias, float* __restrict__ C,
              __nv_bfloat16* __restrict__ Chi, __nv_bfloat16* __restrict__ Clo,
              int N, int K)
{
    extern __shared__ char smem[];
    const uint32_t sb = smem_u32(smem);
    const int t = threadIdx.x;
    const int wid = t >> 5;
    const int lane = t & 31;
    const int bm = blockIdx.y * 128;
    const int bn = blockIdx.x * 128;
    const int wm = (wid >> 2) * 64;
    const int wn = (wid & 3) * 32;

    float acc[4][4][4];
    #pragma unroll
    for (int mt = 0; mt < 4; mt++)
        #pragma unroll
        for (int nt = 0; nt < 4; nt++)
            #pragma unroll
            for (int j = 0; j < 4; j++) acc[mt][nt][j] = 0.f;

    const int niter = K >> 6;   // K/64

    gemm_issue(sb, Ah, Al, Bh, Bl, bm, bn, K, t, 0);

    for (int c = 0; c < niter; c++) {
        if (c + 1 < niter) {
            gemm_issue(sb + ((c + 1) & 1) * GSTAGE2, Ah, Al, Bh, Bl, bm, bn, K, t, c + 1);
            CP_WAIT(1);
        } else {
            CP_WAIT(0);
        }
        __syncthreads();

        const uint32_t stage = sb + (c & 1) * GSTAGE2;
        #pragma unroll
        for (int ks = 0; ks < 4; ks++) {
            uint32_t ah[4][4], al[4][4], bh[4][2], bl[4][2];
            #pragma unroll
            for (int mt = 0; mt < 4; mt++) {
                uint32_t off = sw128(wm + mt * 16 + (lane & 15), ks * 2 + (lane >> 4));
                ldm_x4(ah[mt], stage + off);
                ldm_x4(al[mt], stage + GT2 + off);
            }
            #pragma unroll
            for (int nt = 0; nt < 4; nt++) {
                uint32_t off = sw128(wn + nt * 8 + (lane & 7), ks * 2 + ((lane >> 3) & 1));
                ldm_x2(bh[nt], stage + 2 * GT2 + off);
                ldm_x2(bl[nt], stage + 3 * GT2 + off);
            }
            #pragma unroll
            for (int mt = 0; mt < 4; mt++)
                #pragma unroll
                for (int nt = 0; nt < 4; nt++) {
                    mma16816(acc[mt][nt], ah[mt], bh[nt]);
                    mma16816(acc[mt][nt], ah[mt], bl[nt]);
                    mma16816(acc[mt][nt], al[mt], bh[nt]);
                }
        }
        __syncthreads();
    }

    // epilogue
    #pragma unroll
    for (int mt = 0; mt < 4; mt++) {
        const int r0 = bm + wm + mt * 16 + (lane >> 2);
        #pragma unroll
        for (int nt = 0; nt < 4; nt++) {
            const int col = bn + wn + nt * 8 + (lane & 3) * 2;
            const float b0 = bias[col], b1 = bias[col + 1];
            float v00 = acc[mt][nt][0] + b0, v01 = acc[mt][nt][1] + b1;
            float v10 = acc[mt][nt][2] + b0, v11 = acc[mt][nt][3] + b1;
            if (MODE == 0) {
                *(float2*)&C[(size_t)r0 * N + col] = make_float2(v00, v01);
                *(float2*)&C[(size_t)(r0 + 8) * N + col] = make_float2(v10, v11);
            } else {
                __nv_bfloat16 h00 = __float2bfloat16_rn(v00);
                __nv_bfloat16 h01 = __float2bfloat16_rn(v01);
                __nv_bfloat16 h10 = __float2bfloat16_rn(v10);
                __nv_bfloat16 h11 = __float2bfloat16_rn(v11);
                *(uint32_t*)&Chi[(size_t)r0 * N + col] = pkh(h00, h01);
                *(uint32_t*)&Chi[(size_t)(r0 + 8) * N + col] = pkh(h10, h11);
                *(uint32_t*)&Clo[(size_t)r0 * N + col] =
                    pk2(v00 - __bfloat162float(h00), v01 - __bfloat162float(h01));
                *(uint32_t*)&Clo[(size_t)(r0 + 8) * N + col] =
                    pk2(v10 - __bfloat162float(h10), v11 - __bfloat162float(h11));
            }
        }
    }
}

// ---------------------------------------------------------------------------
// HMMA flash attention, pre-split bf16 inputs, cp.async double buffer.
// CTA = 64 q-rows of one (b,h), 4 warps. smem: Qh Ql + 2 stages{Kh Kl Vh Vl}.
// ---------------------------------------------------------------------------
#define AT      8192                  // 64 rows x 128B
#define ASTAGE  (4 * AT)              // 32768
#define ASMEM   (2 * AT + 2 * ASTAGE) // 81920

__device__ __forceinline__ void attn_issue_kv(uint32_t sdst, int b, int h, int kt, int t)
{
    const size_t base_off = ((size_t)(b * S_ + kt * 64) * TE_ + h * (3 * D_)) * 2;
    #pragma unroll
    for (int i = 0; i < 16; i++) {
        const int tile = i >> 2;                  // 0:Kh 1:Kl 2:Vh 3:Vl
        const int row = (i & 3) * 16 + (t >> 3);  // 0..63
        const int kg = t & 7;
        const __nv_bfloat16* arr = (tile & 1) ? g_qkv_lo : g_qkv_hi;
        const size_t go = base_off + (size_t)row * (TE_ * 2)
                        + (tile < 2 ? D_ : 2 * D_) * 2 + kg * 16;
        cp_async16(sdst + (uint32_t)tile * AT + sw128(row, kg), (const char*)arr + go);
    }
    cp_commit();
}

__global__ __launch_bounds__(128, 2)
void flash_mma()
{
    extern __shared__ char smem[];
    const uint32_t sb = smem_u32(smem);
    const uint32_t sQh = sb, sQl = sb + AT;

    const int t = threadIdx.x;
    const int wid = t >> 5;
    const int lane = t & 31;
    const int qt = blockIdx.x, h = blockIdx.y, b = blockIdx.z;

    // prologue: Q group, then KV stage 0
    {
        const size_t qbase = ((size_t)(b * S_ + qt * 64) * TE_ + h * (3 * D_)) * 2;
        #pragma unroll
        for (int i = 0; i < 8; i++) {
            const int tile = i >> 2;              // 0:Qh 1:Ql
            const int row = (i & 3) * 16 + (t >> 3);
            const int kg = t & 7;
            const __nv_bfloat16* arr = tile ? g_qkv_lo : g_qkv_hi;
            const size_t go = qbase + (size_t)row * (TE_ * 2) + kg * 16;
            cp_async16(sb + (uint32_t)tile * AT + sw128(row, kg), (const char*)arr + go);
        }
        cp_commit();
    }
    attn_issue_kv(sb + 2 * AT, b, h, 0, t);

    CP_WAIT(1);            // Q landed
    __syncthreads();

    uint32_t aqh[4][4], aql[4][4];
    #pragma unroll
    for (int ks = 0; ks < 4; ks++) {
        uint32_t off = sw128(wid * 16 + (lane & 15), ks * 2 + (lane >> 4));
        ldm_x4(aqh[ks], sQh + off);
        ldm_x4(aql[ks], sQl + off);
    }

    float o[8][4];
    #pragma unroll
    for (int nt = 0; nt < 8; nt++)
        #pragma unroll
        for (int j = 0; j < 4; j++) o[nt][j] = 0.f;
    float m0 = -1e30f, m1 = -1e30f, l0 = 0.f, l1 = 0.f;

    const int NT = S_ / 64;
    for (int kt = 0; kt < NT; kt++) {
        if (kt + 1 < NT) {
            attn_issue_kv(sb + 2 * AT + ((kt + 1) & 1) * ASTAGE, b, h, kt + 1, t);
            CP_WAIT(1);
        } else {
            CP_WAIT(0);
        }
        __syncthreads();

        const uint32_t st = sb + 2 * AT + (kt & 1) * ASTAGE;
        const uint32_t stKh = st, stKl = st + AT, stVh = st + 2 * AT, stVl = st + 3 * AT;

        // ---- S = Q K^T (3-term split, fp32 accum) ----
        float sc[8][4];
        #pragma unroll
        for (int nt = 0; nt < 8; nt++)
            #pragma unroll
            for (int j = 0; j < 4; j++) sc[nt][j] = 0.f;
        #pragma unroll
        for (int ks = 0; ks < 4; ks++) {
            #pragma unroll
            for (int nt = 0; nt < 8; nt++) {
                uint32_t off = sw128(nt * 8 + (lane & 7), ks * 2 + ((lane >> 3) & 1));
                uint32_t bh[2], bl[2];
                ldm_x2(bh, stKh + off);
                ldm_x2(bl, stKl + off);
                mma16816(sc[nt], aqh[ks], bh);
                mma16816(sc[nt], aqh[ks], bl);
                mma16816(sc[nt], aql[ks], bh);
            }
        }
        // fold 1/sqrt(D) into scores (exact: power of two)
        #pragma unroll
        for (int nt = 0; nt < 8; nt++) {
            sc[nt][0] *= 0.125f; sc[nt][1] *= 0.125f;
            sc[nt][2] *= 0.125f; sc[nt][3] *= 0.125f;
        }

        // ---- online softmax ----
        float rx0 = -1e30f, rx1 = -1e30f;
        #pragma unroll
        for (int nt = 0; nt < 8; nt++) {
            rx0 = fmaxf(rx0, fmaxf(sc[nt][0], sc[nt][1]));
            rx1 = fmaxf(rx1, fmaxf(sc[nt][2], sc[nt][3]));
        }
        rx0 = fmaxf(rx0, __shfl_xor_sync(0xffffffffu, rx0, 1));
        rx0 = fmaxf(rx0, __shfl_xor_sync(0xffffffffu, rx0, 2));
        rx1 = fmaxf(rx1, __shfl_xor_sync(0xffffffffu, rx1, 1));
        rx1 = fmaxf(rx1, __shfl_xor_sync(0xffffffffu, rx1, 2));

        const float mn0 = fmaxf(m0, rx0), mn1 = fmaxf(m1, rx1);
        const float s0 = __expf(m0 - mn0), s1 = __expf(m1 - mn1);
        m0 = mn0; m1 = mn1;
        #pragma unroll
        for (int nt = 0; nt < 8; nt++) {
            o[nt][0] *= s0; o[nt][1] *= s0;
            o[nt][2] *= s1; o[nt][3] *= s1;
        }
        float sum0 = 0.f, sum1 = 0.f;
        #pragma unroll
        for (int nt = 0; nt < 8; nt++) {
            sc[nt][0] = __expf(sc[nt][0] - mn0);
            sc[nt][1] = __expf(sc[nt][1] - mn0);
            sc[nt][2] = __expf(sc[nt][2] - mn1);
            sc[nt][3] = __expf(sc[nt][3] - mn1);
            sum0 += sc[nt][0] + sc[nt][1];
            sum1 += sc[nt][2] + sc[nt][3];
        }
        sum0 += __shfl_xor_sync(0xffffffffu, sum0, 1);
        sum0 += __shfl_xor_sync(0xffffffffu, sum0, 2);
        sum1 += __shfl_xor_sync(0xffffffffu, sum1, 1);
        sum1 += __shfl_xor_sync(0xffffffffu, sum1, 2);
        l0 = l0 * s0 + sum0;
        l1 = l1 * s1 + sum1;

        // ---- O += P V (3-term split) ----
        #pragma unroll
        for (int ks = 0; ks < 4; ks++) {
            uint32_t aph[4], apl[4];
            {
                const int j0 = 2 * ks, j1 = 2 * ks + 1;
                __nv_bfloat16 h00 = __float2bfloat16_rn(sc[j0][0]);
                __nv_bfloat16 h01 = __float2bfloat16_rn(sc[j0][1]);
                __nv_bfloat16 h02 = __float2bfloat16_rn(sc[j0][2]);
                __nv_bfloat16 h03 = __float2bfloat16_rn(sc[j0][3]);
                __nv_bfloat16 h10 = __float2bfloat16_rn(sc[j1][0]);
                __nv_bfloat16 h11 = __float2bfloat16_rn(sc[j1][1]);
                __nv_bfloat16 h12 = __float2bfloat16_rn(sc[j1][2]);
                __nv_bfloat16 h13 = __float2bfloat16_rn(sc[j1][3]);
                aph[0] = pkh(h00, h01);
                aph[1] = pkh(h02, h03);
                aph[2] = pkh(h10, h11);
                aph[3] = pkh(h12, h13);
                apl[0] = pk2(sc[j0][0] - __bfloat162float(h00), sc[j0][1] - __bfloat162float(h01));
                apl[1] = pk2(sc[j0][2] - __bfloat162float(h02), sc[j0][3] - __bfloat162float(h03));
                apl[2] = pk2(sc[j1][0] - __bfloat162float(h10), sc[j1][1] - __bfloat162float(h11));
                apl[3] = pk2(sc[j1][2] - __bfloat162float(h12), sc[j1][3] - __bfloat162float(h13));
            }
            #pragma unroll
            for (int nt = 0; nt < 8; nt++) {
                uint32_t off = sw128(ks * 16 + (lane & 15), nt);
                uint32_t bh[2], bl[2];
                ldm_x2t(bh, stVh + off);
                ldm_x2t(bl, stVl + off);
                mma16816(o[nt], aph, bh);
                mma16816(o[nt], aph, bl);
                mma16816(o[nt], apl, bh);
            }
        }
        __syncthreads();
    }

    // ---- normalize, split hi/lo, store ----
    const float inv0 = 1.f / l0, inv1 = 1.f / l1;
    const int r0 = b * S_ + qt * 64 + wid * 16 + (lane >> 2);
    #pragma unroll
    for (int nt = 0; nt < 8; nt++) {
        const int col = h * D_ + nt * 8 + (lane & 3) * 2;
        float v00 = o[nt][0] * inv0, v01 = o[nt][1] * inv0;
        float v10 = o[nt][2] * inv1, v11 = o[nt][3] * inv1;
        __nv_bfloat16 h00 = __float2bfloat16_rn(v00);
        __nv_bfloat16 h01 = __float2bfloat16_rn(v01);
        __nv_bfloat16 h10 = __float2bfloat16_rn(v10);
        __nv_bfloat16 h11 = __float2bfloat16_rn(v11);
        *(uint32_t*)&g_o_hi[(size_t)r0 * E_ + col] = pkh(h00, h01);
        *(uint32_t*)&g_o_hi[(size_t)(r0 + 8) * E_ + col] = pkh(h10, h11);
        *(uint32_t*)&g_o_lo[(size_t)r0 * E_ + col] =
            pk2(v00 - __bfloat162float(h00), v01 - __bfloat162float(h01));
        *(uint32_t*)&g_o_lo[(size_t)(r0 + 8) * E_ + col] =
            pk2(v10 - __bfloat162float(h10), v11 - __bfloat162float(h11));
    }
}

// ---------------------------------------------------------------------------
// Launch
// ---------------------------------------------------------------------------
extern "C" void kernel_launch(void* const* d_in, const int* in_sizes, int n_in,
                              void* d_out, int out_size)
{
    const float* x     = (const float*)d_in[0];
    const float* w_qkv = (const float*)d_in[1];
    const float* b_qkv = (const float*)d_in[2];
    const float* w_o   = (const float*)d_in[3];
    const float* b_o   = (const float*)d_in[4];
    float* out = (float*)d_out;

    __nv_bfloat16 *qkv_hi, *qkv_lo, *o_hi, *o_lo;
    __nv_bfloat16 *x_hi, *x_lo, *wq_hi, *wq_lo, *wo_hi, *wo_lo;
    cudaGetSymbolAddress((void**)&qkv_hi, g_qkv_hi);
    cudaGetSymbolAddress((void**)&qkv_lo, g_qkv_lo);
    cudaGetSymbolAddress((void**)&o_hi, g_o_hi);
    cudaGetSymbolAddress((void**)&o_lo, g_o_lo);
    cudaGetSymbolAddress((void**)&x_hi, g_x_hi);
    cudaGetSymbolAddress((void**)&x_lo, g_x_lo);
    cudaGetSymbolAddress((void**)&wq_hi, g_wq_hi);
    cudaGetSymbolAddress((void**)&wq_lo, g_wq_lo);
    cudaGetSymbolAddress((void**)&wo_hi, g_wo_hi);
    cudaGetSymbolAddress((void**)&wo_lo, g_wo_lo);

    cudaFuncSetAttribute(gemm_mma<0>, cudaFuncAttributeMaxDynamicSharedMemorySize, GSMEM2);
    cudaFuncSetAttribute(gemm_mma<1>, cudaFuncAttributeMaxDynamicSharedMemorySize, GSMEM2);
    cudaFuncSetAttribute(flash_mma, cudaFuncAttributeMaxDynamicSharedMemorySize, ASMEM);

    {
        int n4 = (MTOT * E_) / 4;
        split_bf16x2<<<(n4 + 255) / 256, 256>>>(x, x_hi, x_lo, n4);
        n4 = (TE_ * E_) / 4;
        split_bf16x2<<<(n4 + 255) / 256, 256>>>(w_qkv, wq_hi, wq_lo, n4);
        n4 = (E_ * E_) / 4;
        split_bf16x2<<<(n4 + 255) / 256, 256>>>(w_o, wo_hi, wo_lo, n4);
    }

    {
        dim3 g(TE_ / 128, MTOT / 128);   // 24 x 32
        gemm_mma<1><<<g, 256, GSMEM2>>>(x_hi, x_lo, wq_hi, wq_lo, b_qkv,
                                        nullptr, qkv_hi, qkv_lo, TE_, E_);
    }
    {
        dim3 g(S_ / 64, H_, B_);          // 32 x 16 x 2
        flash_mma<<<g, 128, ASMEM>>>();
    }
    {
        dim3 g(E_ / 128, MTOT / 128);     // 8 x 32
        gemm_mma<0><<<g, 256, GSMEM2>>>(o_hi, o_lo, wo_hi, wo_lo, b_o,
                                        out, nullptr, nullptr, E_, E_);
    }
}

// round 5
// speedup vs baseline: 8.4008x; 1.0750x over previous
#include <cuda_runtime.h>
#include <cuda_bf16.h>
#include <cstdint>

#define B_   2
#define S_   2048
#define H_   16
#define D_   64
#define E_   1024
#define TE_  3072
#define MTOT (B_ * S_)   // 4096

// ---------------------------------------------------------------------------
// Scratch (__device__ globals; no allocation allowed)
// ---------------------------------------------------------------------------
__device__ __nv_bfloat16 g_qkv_hi[(size_t)MTOT * TE_];
__device__ __nv_bfloat16 g_qkv_lo[(size_t)MTOT * TE_];
__device__ __nv_bfloat16 g_o_hi[(size_t)MTOT * E_];
__device__ __nv_bfloat16 g_o_lo[(size_t)MTOT * E_];
__device__ __nv_bfloat16 g_x_hi[(size_t)MTOT * E_];
__device__ __nv_bfloat16 g_x_lo[(size_t)MTOT * E_];
__device__ __nv_bfloat16 g_wq_hi[(size_t)TE_ * E_];
__device__ __nv_bfloat16 g_wq_lo[(size_t)TE_ * E_];
__device__ __nv_bfloat16 g_wo_hi[(size_t)E_ * E_];
__device__ __nv_bfloat16 g_wo_lo[(size_t)E_ * E_];

// ---------------------------------------------------------------------------
// Helpers (sm_80-level PTX only)
// ---------------------------------------------------------------------------
__device__ __forceinline__ uint32_t smem_u32(const void* p) {
    uint32_t a;
    asm("{ .reg .u64 t; cvta.to.shared.u64 t, %1; cvt.u32.u64 %0, t; }" : "=r"(a) : "l"(p));
    return a;
}
__device__ __forceinline__ uint32_t pk2(float a, float b) {
    __nv_bfloat162 t = __floats2bfloat162_rn(a, b);
    return *reinterpret_cast<uint32_t*>(&t);
}
__device__ __forceinline__ uint32_t pkh(__nv_bfloat16 a, __nv_bfloat16 b) {
    __nv_bfloat162 t(a, b);
    return *reinterpret_cast<uint32_t*>(&t);
}
__device__ __forceinline__ void ldm_x4(uint32_t* r, uint32_t addr) {
    asm volatile("ldmatrix.sync.aligned.m8n8.x4.shared.b16 {%0,%1,%2,%3}, [%4];"
                 : "=r"(r[0]), "=r"(r[1]), "=r"(r[2]), "=r"(r[3]) : "r"(addr));
}
__device__ __forceinline__ void ldm_x4t(uint32_t* r, uint32_t addr) {
    asm volatile("ldmatrix.sync.aligned.m8n8.x4.trans.shared.b16 {%0,%1,%2,%3}, [%4];"
                 : "=r"(r[0]), "=r"(r[1]), "=r"(r[2]), "=r"(r[3]) : "r"(addr));
}
__device__ __forceinline__ void mma16816(float* c, const uint32_t* a, const uint32_t* b) {
    asm volatile(
        "mma.sync.aligned.m16n8k16.row.col.f32.bf16.bf16.f32 "
        "{%0,%1,%2,%3}, {%4,%5,%6,%7}, {%8,%9}, {%0,%1,%2,%3};"
        : "+f"(c[0]), "+f"(c[1]), "+f"(c[2]), "+f"(c[3])
        : "r"(a[0]), "r"(a[1]), "r"(a[2]), "r"(a[3]), "r"(b[0]), "r"(b[1]));
}
__device__ __forceinline__ void cp_async16(uint32_t saddr, const void* gaddr) {
    asm volatile("cp.async.cg.shared.global [%0], [%1], 16;" :: "r"(saddr), "l"(gaddr) : "memory");
}
__device__ __forceinline__ void cp_commit() {
    asm volatile("cp.async.commit_group;" ::: "memory");
}
#define CP_WAIT(n) asm volatile("cp.async.wait_group %0;" :: "n"(n) : "memory")

// 128B-row XOR swizzle (8x16B groups), conflict-free for ldmatrix
__device__ __forceinline__ uint32_t sw128(uint32_t row, uint32_t kg) {
    return row * 128u + ((kg ^ (row & 7u)) << 4);
}

// ---------------------------------------------------------------------------
// fp32 -> bf16 hi + bf16 lo split
// ---------------------------------------------------------------------------
__global__ __launch_bounds__(256)
void split_bf16x2(const float* __restrict__ in, __nv_bfloat16* __restrict__ hi,
                  __nv_bfloat16* __restrict__ lo, int n4)
{
    int i = blockIdx.x * blockDim.x + threadIdx.x;
    if (i >= n4) return;
    float4 v = ((const float4*)in)[i];
    __nv_bfloat16 h0 = __float2bfloat16_rn(v.x);
    __nv_bfloat16 h1 = __float2bfloat16_rn(v.y);
    __nv_bfloat16 h2 = __float2bfloat16_rn(v.z);
    __nv_bfloat16 h3 = __float2bfloat16_rn(v.w);
    uint2 hp = make_uint2(pkh(h0, h1), pkh(h2, h3));
    uint2 lp = make_uint2(pk2(v.x - __bfloat162float(h0), v.y - __bfloat162float(h1)),
                          pk2(v.z - __bfloat162float(h2), v.w - __bfloat162float(h3)));
    *(uint2*)(hi + (size_t)i * 4) = hp;
    *(uint2*)(lo + (size_t)i * 4) = lp;
}

// ---------------------------------------------------------------------------
// HMMA split-bf16 GEMM (NT): C = A[M,K]*B[N,K]^T + bias
// 128x64 block tile, 8 warps (32x32 each, 4x2), BK=64, 2-stage cp.async.
// 2 CTAs/SM (regs<=128 via launch_bounds, 96KB smem/CTA).
// MODE 0: fp32 C.  MODE 1: bf16 hi/lo split outputs.
// ---------------------------------------------------------------------------
#define GA3     16384                 // A tile: 128 rows x 128B
#define GB3     8192                  // B tile: 64 rows x 128B
#define GSTAGE3 (2 * GA3 + 2 * GB3)   // Ah Al Bh Bl = 49152
#define GSMEM3  (2 * GSTAGE3)         // 98304

__device__ __forceinline__ void gemm_issue(
    uint32_t sdst, const __nv_bfloat16* Ah, const __nv_bfloat16* Al,
    const __nv_bfloat16* Bh, const __nv_bfloat16* Bl,
    int bm, int bn, int K, int t, int c)
{
    const int kg = t & 7;
    const int r32 = t >> 3;            // 0..31
    const int koff = c * 128;
    #pragma unroll
    for (int i = 0; i < 4; i++) {      // A hi: rows i*32 + r32
        const int row = i * 32 + r32;
        cp_async16(sdst + sw128(row, kg),
                   (const char*)(Ah + (size_t)(bm + row) * K) + kg * 16 + koff);
        cp_async16(sdst + GA3 + sw128(row, kg),
                   (const char*)(Al + (size_t)(bm + row) * K) + kg * 16 + koff);
    }
    #pragma unroll
    for (int i = 0; i < 2; i++) {      // B: rows i*32 + r32
        const int row = i * 32 + r32;
        cp_async16(sdst + 2 * GA3 + sw128(row, kg),
                   (const char*)(Bh + (size_t)(bn + row) * K) + kg * 16 + koff);
        cp_async16(sdst + 2 * GA3 + GB3 + sw128(row, kg),
                   (const char*)(Bl + (size_t)(bn + row) * K) + kg * 16 + koff);
    }
    cp_commit();
}

template <int MODE>
__global__ __launch_bounds__(256, 2)
void gemm_mma(const __nv_bfloat16* __restrict__ Ah, const __nv_bfloat16* __restrict__ Al,
              const __nv_bfloat16* __restrict__ Bh, const __nv_bfloat16* __restrict__ Bl,
              const float* __restrict__ bias, float* __restrict__ C,
              __nv_bfloat16* __restrict__ Chi, __nv_bfloat16* __restrict__ Clo,
              int N, int K)
{
    extern __shared__ char smem[];
    const uint32_t sb = smem_u32(smem);
    const int t = threadIdx.x;
    const int wid = t >> 5;
    const int lane = t & 31;
    const int bm = blockIdx.y * 128;
    const int bn = blockIdx.x * 64;
    const int wm = (wid >> 1) * 32;    // 0,32,64,96
    const int wn = (wid & 1) * 32;     // 0,32

    float acc[2][4][4];
    #pragma unroll
    for (int mt = 0; mt < 2; mt++)
        #pragma unroll
        for (int nt = 0; nt < 4; nt++)
            #pragma unroll
            for (int j = 0; j < 4; j++) acc[mt][nt][j] = 0.f;

    const int niter = K >> 6;

    gemm_issue(sb, Ah, Al, Bh, Bl, bm, bn, K, t, 0);

    for (int c = 0; c < niter; c++) {
        if (c + 1 < niter) {
            gemm_issue(sb + ((c + 1) & 1) * GSTAGE3, Ah, Al, Bh, Bl, bm, bn, K, t, c + 1);
            CP_WAIT(1);
        } else {
            CP_WAIT(0);
        }
        __syncthreads();

        const uint32_t stage = sb + (c & 1) * GSTAGE3;
        #pragma unroll
        for (int ks = 0; ks < 4; ks++) {
            uint32_t ah[2][4], al[2][4], bh[2][4], bl[2][4];
            #pragma unroll
            for (int mt = 0; mt < 2; mt++) {
                uint32_t off = sw128(wm + mt * 16 + (lane & 15), ks * 2 + (lane >> 4));
                ldm_x4(ah[mt], stage + off);
                ldm_x4(al[mt], stage + GA3 + off);
            }
            #pragma unroll
            for (int p = 0; p < 2; p++) {   // covers nt = 2p, 2p+1
                uint32_t off = sw128(wn + (p * 2 + (lane >> 4)) * 8 + (lane & 7),
                                     ks * 2 + ((lane >> 3) & 1));
                ldm_x4(bh[p], stage + 2 * GA3 + off);
                ldm_x4(bl[p], stage + 2 * GA3 + GB3 + off);
            }
            #pragma unroll
            for (int mt = 0; mt < 2; mt++)
                #pragma unroll
                for (int nt = 0; nt < 4; nt++) {
                    const uint32_t* bhf = &bh[nt >> 1][(nt & 1) * 2];
                    const uint32_t* blf = &bl[nt >> 1][(nt & 1) * 2];
                    mma16816(acc[mt][nt], ah[mt], bhf);
                    mma16816(acc[mt][nt], ah[mt], blf);
                    mma16816(acc[mt][nt], al[mt], bhf);
                }
        }
        __syncthreads();
    }

    // epilogue
    #pragma unroll
    for (int mt = 0; mt < 2; mt++) {
        const int r0 = bm + wm + mt * 16 + (lane >> 2);
        #pragma unroll
        for (int nt = 0; nt < 4; nt++) {
            const int col = bn + wn + nt * 8 + (lane & 3) * 2;
            const float b0 = bias[col], b1 = bias[col + 1];
            float v00 = acc[mt][nt][0] + b0, v01 = acc[mt][nt][1] + b1;
            float v10 = acc[mt][nt][2] + b0, v11 = acc[mt][nt][3] + b1;
            if (MODE == 0) {
                *(float2*)&C[(size_t)r0 * N + col] = make_float2(v00, v01);
                *(float2*)&C[(size_t)(r0 + 8) * N + col] = make_float2(v10, v11);
            } else {
                __nv_bfloat16 h00 = __float2bfloat16_rn(v00);
                __nv_bfloat16 h01 = __float2bfloat16_rn(v01);
                __nv_bfloat16 h10 = __float2bfloat16_rn(v10);
                __nv_bfloat16 h11 = __float2bfloat16_rn(v11);
                *(uint32_t*)&Chi[(size_t)r0 * N + col] = pkh(h00, h01);
                *(uint32_t*)&Chi[(size_t)(r0 + 8) * N + col] = pkh(h10, h11);
                *(uint32_t*)&Clo[(size_t)r0 * N + col] =
                    pk2(v00 - __bfloat162float(h00), v01 - __bfloat162float(h01));
                *(uint32_t*)&Clo[(size_t)(r0 + 8) * N + col] =
                    pk2(v10 - __bfloat162float(h10), v11 - __bfloat162float(h11));
            }
        }
    }
}

// ---------------------------------------------------------------------------
// HMMA flash attention, pre-split bf16 inputs, cp.async double buffer.
// CTA = 64 q-rows of one (b,h), 4 warps. smem: Qh Ql + 2 stages{Kh Kl Vh Vl}.
// ---------------------------------------------------------------------------
#define AT      8192
#define ASTAGE  (4 * AT)
#define ASMEM   (2 * AT + 2 * ASTAGE)   // 81920

__device__ __forceinline__ void attn_issue_kv(uint32_t sdst, int b, int h, int kt, int t)
{
    const size_t base_off = ((size_t)(b * S_ + kt * 64) * TE_ + h * (3 * D_)) * 2;
    #pragma unroll
    for (int i = 0; i < 16; i++) {
        const int tile = i >> 2;                  // 0:Kh 1:Kl 2:Vh 3:Vl
        const int row = (i & 3) * 16 + (t >> 3);
        const int kg = t & 7;
        const __nv_bfloat16* arr = (tile & 1) ? g_qkv_lo : g_qkv_hi;
        const size_t go = base_off + (size_t)row * (TE_ * 2)
                        + (tile < 2 ? D_ : 2 * D_) * 2 + kg * 16;
        cp_async16(sdst + (uint32_t)tile * AT + sw128(row, kg), (const char*)arr + go);
    }
    cp_commit();
}

__global__ __launch_bounds__(128, 2)
void flash_mma()
{
    extern __shared__ char smem[];
    const uint32_t sb = smem_u32(smem);
    const uint32_t sQh = sb, sQl = sb + AT;

    const int t = threadIdx.x;
    const int wid = t >> 5;
    const int lane = t & 31;
    const int qt = blockIdx.x, h = blockIdx.y, b = blockIdx.z;

    {
        const size_t qbase = ((size_t)(b * S_ + qt * 64) * TE_ + h * (3 * D_)) * 2;
        #pragma unroll
        for (int i = 0; i < 8; i++) {
            const int tile = i >> 2;
            const int row = (i & 3) * 16 + (t >> 3);
            const int kg = t & 7;
            const __nv_bfloat16* arr = tile ? g_qkv_lo : g_qkv_hi;
            const size_t go = qbase + (size_t)row * (TE_ * 2) + kg * 16;
            cp_async16(sb + (uint32_t)tile * AT + sw128(row, kg), (const char*)arr + go);
        }
        cp_commit();
    }
    attn_issue_kv(sb + 2 * AT, b, h, 0, t);

    CP_WAIT(1);
    __syncthreads();

    uint32_t aqh[4][4], aql[4][4];
    #pragma unroll
    for (int ks = 0; ks < 4; ks++) {
        uint32_t off = sw128(wid * 16 + (lane & 15), ks * 2 + (lane >> 4));
        ldm_x4(aqh[ks], sQh + off);
        ldm_x4(aql[ks], sQl + off);
    }

    float o[8][4];
    #pragma unroll
    for (int nt = 0; nt < 8; nt++)
        #pragma unroll
        for (int j = 0; j < 4; j++) o[nt][j] = 0.f;
    float m0 = -1e30f, m1 = -1e30f, l0 = 0.f, l1 = 0.f;

    const int NT = S_ / 64;
    for (int kt = 0; kt < NT; kt++) {
        if (kt + 1 < NT) {
            attn_issue_kv(sb + 2 * AT + ((kt + 1) & 1) * ASTAGE, b, h, kt + 1, t);
            CP_WAIT(1);
        } else {
            CP_WAIT(0);
        }
        __syncthreads();

        const uint32_t st = sb + 2 * AT + (kt & 1) * ASTAGE;
        const uint32_t stKh = st, stKl = st + AT, stVh = st + 2 * AT, stVl = st + 3 * AT;

        // ---- S = Q K^T (3-term split, fp32 accum); x4-fused K loads ----
        float sc[8][4];
        #pragma unroll
        for (int nt = 0; nt < 8; nt++)
            #pragma unroll
            for (int j = 0; j < 4; j++) sc[nt][j] = 0.f;
        #pragma unroll
        for (int ks = 0; ks < 4; ks++) {
            #pragma unroll
            for (int p = 0; p < 4; p++) {      // covers nt = 2p, 2p+1
                uint32_t off = sw128((p * 2 + (lane >> 4)) * 8 + (lane & 7),
                                     ks * 2 + ((lane >> 3) & 1));
                uint32_t bh[4], bl[4];
                ldm_x4(bh, stKh + off);
                ldm_x4(bl, stKl + off);
                mma16816(sc[2 * p], aqh[ks], bh);
                mma16816(sc[2 * p], aqh[ks], bl);
                mma16816(sc[2 * p], aql[ks], bh);
                mma16816(sc[2 * p + 1], aqh[ks], bh + 2);
                mma16816(sc[2 * p + 1], aqh[ks], bl + 2);
                mma16816(sc[2 * p + 1], aql[ks], bh + 2);
            }
        }
        #pragma unroll
        for (int nt = 0; nt < 8; nt++) {
            sc[nt][0] *= 0.125f; sc[nt][1] *= 0.125f;
            sc[nt][2] *= 0.125f; sc[nt][3] *= 0.125f;
        }

        // ---- online softmax ----
        float rx0 = -1e30f, rx1 = -1e30f;
        #pragma unroll
        for (int nt = 0; nt < 8; nt++) {
            rx0 = fmaxf(rx0, fmaxf(sc[nt][0], sc[nt][1]));
            rx1 = fmaxf(rx1, fmaxf(sc[nt][2], sc[nt][3]));
        }
        rx0 = fmaxf(rx0, __shfl_xor_sync(0xffffffffu, rx0, 1));
        rx0 = fmaxf(rx0, __shfl_xor_sync(0xffffffffu, rx0, 2));
        rx1 = fmaxf(rx1, __shfl_xor_sync(0xffffffffu, rx1, 1));
        rx1 = fmaxf(rx1, __shfl_xor_sync(0xffffffffu, rx1, 2));

        const float mn0 = fmaxf(m0, rx0), mn1 = fmaxf(m1, rx1);
        const float s0 = __expf(m0 - mn0), s1 = __expf(m1 - mn1);
        m0 = mn0; m1 = mn1;
        #pragma unroll
        for (int nt = 0; nt < 8; nt++) {
            o[nt][0] *= s0; o[nt][1] *= s0;
            o[nt][2] *= s1; o[nt][3] *= s1;
        }
        float sum0 = 0.f, sum1 = 0.f;
        #pragma unroll
        for (int nt = 0; nt < 8; nt++) {
            sc[nt][0] = __expf(sc[nt][0] - mn0);
            sc[nt][1] = __expf(sc[nt][1] - mn0);
            sc[nt][2] = __expf(sc[nt][2] - mn1);
            sc[nt][3] = __expf(sc[nt][3] - mn1);
            sum0 += sc[nt][0] + sc[nt][1];
            sum1 += sc[nt][2] + sc[nt][3];
        }
        sum0 += __shfl_xor_sync(0xffffffffu, sum0, 1);
        sum0 += __shfl_xor_sync(0xffffffffu, sum0, 2);
        sum1 += __shfl_xor_sync(0xffffffffu, sum1, 1);
        sum1 += __shfl_xor_sync(0xffffffffu, sum1, 2);
        l0 = l0 * s0 + sum0;
        l1 = l1 * s1 + sum1;

        // ---- O += P V (3-term split); x4.trans-fused V loads ----
        #pragma unroll
        for (int ks = 0; ks < 4; ks++) {
            uint32_t aph[4], apl[4];
            {
                const int j0 = 2 * ks, j1 = 2 * ks + 1;
                __nv_bfloat16 h00 = __float2bfloat16_rn(sc[j0][0]);
                __nv_bfloat16 h01 = __float2bfloat16_rn(sc[j0][1]);
                __nv_bfloat16 h02 = __float2bfloat16_rn(sc[j0][2]);
                __nv_bfloat16 h03 = __float2bfloat16_rn(sc[j0][3]);
                __nv_bfloat16 h10 = __float2bfloat16_rn(sc[j1][0]);
                __nv_bfloat16 h11 = __float2bfloat16_rn(sc[j1][1]);
                __nv_bfloat16 h12 = __float2bfloat16_rn(sc[j1][2]);
                __nv_bfloat16 h13 = __float2bfloat16_rn(sc[j1][3]);
                aph[0] = pkh(h00, h01);
                aph[1] = pkh(h02, h03);
                aph[2] = pkh(h10, h11);
                aph[3] = pkh(h12, h13);
                apl[0] = pk2(sc[j0][0] - __bfloat162float(h00), sc[j0][1] - __bfloat162float(h01));
                apl[1] = pk2(sc[j0][2] - __bfloat162float(h02), sc[j0][3] - __bfloat162float(h03));
                apl[2] = pk2(sc[j1][0] - __bfloat162float(h10), sc[j1][1] - __bfloat162float(h11));
                apl[3] = pk2(sc[j1][2] - __bfloat162float(h12), sc[j1][3] - __bfloat162float(h13));
            }
            #pragma unroll
            for (int p = 0; p < 4; p++) {      // covers nt = 2p, 2p+1
                uint32_t off = sw128(ks * 16 + (lane & 15), 2 * p + (lane >> 4));
                uint32_t bh[4], bl[4];
                ldm_x4t(bh, stVh + off);
                ldm_x4t(bl, stVl + off);
                mma16816(o[2 * p], aph, bh);
                mma16816(o[2 * p], aph, bl);
                mma16816(o[2 * p], apl, bh);
                mma16816(o[2 * p + 1], aph, bh + 2);
                mma16816(o[2 * p + 1], aph, bl + 2);
                mma16816(o[2 * p + 1], apl, bh + 2);
            }
        }
        __syncthreads();
    }

    // ---- normalize, split hi/lo, store ----
    const float inv0 = 1.f / l0, inv1 = 1.f / l1;
    const int r0 = b * S_ + qt * 64 + wid * 16 + (lane >> 2);
    #pragma unroll
    for (int nt = 0; nt < 8; nt++) {
        const int col = h * D_ + nt * 8 + (lane & 3) * 2;
        float v00 = o[nt][0] * inv0, v01 = o[nt][1] * inv0;
        float v10 = o[nt][2] * inv1, v11 = o[nt][3] * inv1;
        __nv_bfloat16 h00 = __float2bfloat16_rn(v00);
        __nv_bfloat16 h01 = __float2bfloat16_rn(v01);
        __nv_bfloat16 h10 = __float2bfloat16_rn(v10);
        __nv_bfloat16 h11 = __float2bfloat16_rn(v11);
        *(uint32_t*)&g_o_hi[(size_t)r0 * E_ + col] = pkh(h00, h01);
        *(uint32_t*)&g_o_hi[(size_t)(r0 + 8) * E_ + col] = pkh(h10, h11);
        *(uint32_t*)&g_o_lo[(size_t)r0 * E_ + col] =
            pk2(v00 - __bfloat162float(h00), v01 - __bfloat162float(h01));
        *(uint32_t*)&g_o_lo[(size_t)(r0 + 8) * E_ + col] =
            pk2(v10 - __bfloat162float(h10), v11 - __bfloat162float(h11));
    }
}

// ---------------------------------------------------------------------------
// Launch
// ---------------------------------------------------------------------------
extern "C" void kernel_launch(void* const* d_in, const int* in_sizes, int n_in,
                              void* d_out, int out_size)
{
    const float* x     = (const float*)d_in[0];
    const float* w_qkv = (const float*)d_in[1];
    const float* b_qkv = (const float*)d_in[2];
    const float* w_o   = (const float*)d_in[3];
    const float* b_o   = (const float*)d_in[4];
    float* out = (float*)d_out;

    __nv_bfloat16 *qkv_hi, *qkv_lo, *o_hi, *o_lo;
    __nv_bfloat16 *x_hi, *x_lo, *wq_hi, *wq_lo, *wo_hi, *wo_lo;
    cudaGetSymbolAddress((void**)&qkv_hi, g_qkv_hi);
    cudaGetSymbolAddress((void**)&qkv_lo, g_qkv_lo);
    cudaGetSymbolAddress((void**)&o_hi, g_o_hi);
    cudaGetSymbolAddress((void**)&o_lo, g_o_lo);
    cudaGetSymbolAddress((void**)&x_hi, g_x_hi);
    cudaGetSymbolAddress((void**)&x_lo, g_x_lo);
    cudaGetSymbolAddress((void**)&wq_hi, g_wq_hi);
    cudaGetSymbolAddress((void**)&wq_lo, g_wq_lo);
    cudaGetSymbolAddress((void**)&wo_hi, g_wo_hi);
    cudaGetSymbolAddress((void**)&wo_lo, g_wo_lo);

    cudaFuncSetAttribute(gemm_mma<0>, cudaFuncAttributeMaxDynamicSharedMemorySize, GSMEM3);
    cudaFuncSetAttribute(gemm_mma<1>, cudaFuncAttributeMaxDynamicSharedMemorySize, GSMEM3);
    cudaFuncSetAttribute(flash_mma, cudaFuncAttributeMaxDynamicSharedMemorySize, ASMEM);

    {
        int n4 = (MTOT * E_) / 4;
        split_bf16x2<<<(n4 + 255) / 256, 256>>>(x, x_hi, x_lo, n4);
        n4 = (TE_ * E_) / 4;
        split_bf16x2<<<(n4 + 255) / 256, 256>>>(w_qkv, wq_hi, wq_lo, n4);
        n4 = (E_ * E_) / 4;
        split_bf16x2<<<(n4 + 255) / 256, 256>>>(w_o, wo_hi, wo_lo, n4);
    }

    {
        dim3 g(TE_ / 64, MTOT / 128);    // 48 x 32
        gemm_mma<1><<<g, 256, GSMEM3>>>(x_hi, x_lo, wq_hi, wq_lo, b_qkv,
                                        nullptr, qkv_hi, qkv_lo, TE_, E_);
    }
    {
        dim3 g(S_ / 64, H_, B_);          // 32 x 16 x 2
        flash_mma<<<g, 128, ASMEM>>>();
    }
    {
        dim3 g(E_ / 64, MTOT / 128);      // 16 x 32
        gemm_mma<0><<<g, 256, GSMEM3>>>(o_hi, o_lo, wo_hi, wo_lo, b_o,
                                        out, nullptr, nullptr, E_, E_);
    }
}